// round 4
// baseline (speedup 1.0000x reference)
#include <cuda_runtime.h>
#include <cuda_bf16.h>
#include <math.h>

#define T_LEN     4096
#define DMODEL    2048
#define HKN       16
#define HVN       32
#define DKD       128
#define DVD       128
#define NCHUNK    64
#define QKVZ_COLS 12288
#define SCALE_QK  0.08838834764831845f   // 1/sqrt(128)

#define USE_F32X2 1   // packed fp32 FMA (sm_100+); set 0 for scalar fallback

typedef unsigned long long ull;

// ------------------------- device scratch ----------------------------------
__device__ __align__(16) float g_qkvz[T_LEN * QKVZ_COLS];
__device__ __align__(16) float g_ba  [T_LEN * 64];
__device__ __align__(16) float g_qn  [T_LEN * 2048];
__device__ __align__(16) float g_kn  [T_LEN * 2048];
__device__ __align__(16) float g_v   [T_LEN * 4096];
__device__ __align__(16) float g_gv  [T_LEN * HVN];
__device__ __align__(16) float g_bv  [T_LEN * HVN];
__device__ __align__(16) float g_A   [HVN * NCHUNK * 64 * 64];
__device__ __align__(16) float g_u0  [HVN * NCHUNK * 64 * 128];
__device__ __align__(16) float g_W   [HVN * NCHUNK * 64 * 128];
__device__ __align__(16) float g_qds [HVN * NCHUNK * 64];
__device__ __align__(16) float g_kds [HVN * NCHUNK * 64];
__device__ __align__(16) float g_gce [HVN * NCHUNK];
__device__ __align__(16) float g_o   [T_LEN * 4096];
__device__ __align__(16) float g_xg  [T_LEN * 4096];

// ------------------------- packed-pair FMA helpers --------------------------
struct fpair { float x, y; };

__device__ __forceinline__ void fma2(fpair& d, float a, const fpair& b) {
#if USE_F32X2
    ull dd, bb;
    asm("mov.b64 %0, {%1, %2};" : "=l"(dd) : "f"(d.x), "f"(d.y));
    asm("mov.b64 %0, {%1, %2};" : "=l"(bb) : "f"(b.x), "f"(b.y));
    ull aa;
    asm("mov.b64 %0, {%1, %1};" : "=l"(aa) : "f"(a));
    asm("fma.rn.f32x2 %0, %1, %2, %0;" : "+l"(dd) : "l"(aa), "l"(bb));
    asm("mov.b64 {%0, %1}, %2;" : "=f"(d.x), "=f"(d.y) : "l"(dd));
#else
    d.x = fmaf(a, b.x, d.x);
    d.y = fmaf(a, b.y, d.y);
#endif
}

// ------------------------- SGEMM -------------------------------------------
// C[M,N] = A[M,K] @ B[K,N], row-major. Assumes M%BM==0, N%BN==0, K%BK==0.
template<int BM, int BN, int BK, int TM, int TN>
__global__ __launch_bounds__(256) void sgemm_kernel(
    const float* __restrict__ A, const float* __restrict__ B,
    float* __restrict__ C, int M, int N, int K)
{
    __shared__ float As[BK][BM];
    __shared__ float Bs[BK][BN];
    const int THREADS = (BM / TM) * (BN / TN);   // 256
    int tid = threadIdx.x;
    int bm = blockIdx.y * BM, bn = blockIdx.x * BN;
    int tm = (tid / (BN / TN)) * TM;
    int tn = (tid % (BN / TN)) * TN;

    fpair acc[TM][TN / 2];
#pragma unroll
    for (int i = 0; i < TM; i++)
#pragma unroll
        for (int j = 0; j < TN / 2; j++) { acc[i][j].x = 0.f; acc[i][j].y = 0.f; }

    for (int k0 = 0; k0 < K; k0 += BK) {
#pragma unroll
        for (int l = tid * 4; l < BM * BK; l += THREADS * 4) {
            int row = l / BK, kk = l % BK;
            float4 av = *reinterpret_cast<const float4*>(
                A + (size_t)(bm + row) * K + k0 + kk);
            As[kk + 0][row] = av.x; As[kk + 1][row] = av.y;
            As[kk + 2][row] = av.z; As[kk + 3][row] = av.w;
        }
#pragma unroll
        for (int l = tid * 4; l < BK * BN; l += THREADS * 4) {
            int rr = l / BN, cc = l % BN;
            *reinterpret_cast<float4*>(&Bs[rr][cc]) =
                *reinterpret_cast<const float4*>(B + (size_t)(k0 + rr) * N + bn + cc);
        }
        __syncthreads();
#pragma unroll
        for (int kk = 0; kk < BK; kk++) {
            float  ar[TM];
            fpair  br[TN / 2];
#pragma unroll
            for (int i = 0; i < TM; i++) ar[i] = As[kk][tm + i];
#pragma unroll
            for (int j = 0; j < TN / 2; j++)
                br[j] = *reinterpret_cast<const fpair*>(&Bs[kk][tn + 2 * j]);
#pragma unroll
            for (int i = 0; i < TM; i++)
#pragma unroll
                for (int j = 0; j < TN / 2; j++) fma2(acc[i][j], ar[i], br[j]);
        }
        __syncthreads();
    }
#pragma unroll
    for (int i = 0; i < TM; i++)
#pragma unroll
        for (int j = 0; j < TN / 2; j++) {
            float2 v = make_float2(acc[i][j].x, acc[i][j].y);
            *reinterpret_cast<float2*>(
                C + (size_t)(bm + tm + i) * N + bn + tn + 2 * j) = v;
        }
}

// ------------------------- conv (K=4 causal) + silu -------------------------
__global__ void conv_kernel(const float* __restrict__ conv_w) {
    int idx = blockIdx.x * 256 + threadIdx.x;        // over T*8192
    int t = idx >> 13, c = idx & 8191;
    int col, didx; float* dst;
    if (c < 2048) {                                   // q part
        int h = c >> 7, d = c & 127;
        col = h * 768 + d; dst = g_qn; didx = t * 2048 + c;
    } else if (c < 4096) {                            // k part
        int cc = c - 2048; int h = cc >> 7, d = cc & 127;
        col = h * 768 + 128 + d; dst = g_kn; didx = t * 2048 + cc;
    } else {                                          // v part
        int i = c - 4096; int hv = i >> 7, d = i & 127;
        col = (hv >> 1) * 768 + 256 + (hv & 1) * 128 + d;
        dst = g_v; didx = t * 4096 + i;
    }
    float w0 = conv_w[c * 4 + 0], w1 = conv_w[c * 4 + 1];
    float w2 = conv_w[c * 4 + 2], w3 = conv_w[c * 4 + 3];
    float acc = w3 * g_qkvz[(size_t)t * QKVZ_COLS + col];
    if (t >= 1) acc += w2 * g_qkvz[(size_t)(t - 1) * QKVZ_COLS + col];
    if (t >= 2) acc += w1 * g_qkvz[(size_t)(t - 2) * QKVZ_COLS + col];
    if (t >= 3) acc += w0 * g_qkvz[(size_t)(t - 3) * QKVZ_COLS + col];
    dst[didx] = acc / (1.f + expf(-acc));             // silu
}

// ------------------------- block-128 sum helper -----------------------------
__device__ __forceinline__ float blocksum128(float v) {
#pragma unroll
    for (int o = 16; o; o >>= 1) v += __shfl_xor_sync(0xffffffffu, v, o);
    __shared__ float ws[4];
    if ((threadIdx.x & 31) == 0) ws[threadIdx.x >> 5] = v;
    __syncthreads();
    return ws[0] + ws[1] + ws[2] + ws[3];
}

// ------------------------- l2norm over 128 (in place) -----------------------
__global__ void l2norm_kernel() {
    float* p = blockIdx.y ? g_kn : g_qn;
    size_t base = (size_t)blockIdx.x * 128;
    float v = p[base + threadIdx.x];
    float tot = blocksum128(v * v);
    p[base + threadIdx.x] = v * rsqrtf(tot + 1e-6f);
}

// ------------------------- beta / g ----------------------------------------
__global__ void gbeta_kernel(const float* __restrict__ A_log,
                             const float* __restrict__ dt_bias) {
    int idx = blockIdx.x * 256 + threadIdx.x;        // < T*32
    int t = idx >> 5, hv = idx & 31, hk = hv >> 1, r = hv & 1;
    float b = g_ba[t * 64 + hk * 4 + r];
    float a = g_ba[t * 64 + hk * 4 + 2 + r];
    g_bv[idx] = 1.f / (1.f + expf(-b));
    float x = a + dt_bias[hv];
    float sp = (x > 20.f) ? x : log1pf(expf(x));
    g_gv[idx] = -expf(A_log[hv]) * sp;
}

// ------------------------- per-(chunk,head) precompute ----------------------
// A (masked), u0 = T^-1(beta*v), W = T^-1(beta*e^G*k), qds, kds, gce.
__global__ __launch_bounds__(256) void precompute_kernel() {
    extern __shared__ float psm[];
    float* sk = psm;                 // 64*129
    float* sq = sk + 64 * 129;       // 64*129
    float* sM = sq + 64 * 129;       // 64*64
    __shared__ float sG[64], sB[64];
    int n = blockIdx.x, hv = blockIdx.y, hk = hv >> 1;
    int tid = threadIdx.x;

    if (tid < 64) {
        int t = n * 64 + tid;
        sB[tid] = g_bv[t * 32 + hv];
        sG[tid] = g_gv[t * 32 + hv];
    }
    for (int l = tid; l < 8192; l += 256) {
        int t = l >> 7, d = l & 127;
        size_t row = (size_t)(n * 64 + t) * 2048 + hk * 128 + d;
        sk[t * 129 + d] = g_kn[row];
        sq[t * 129 + d] = g_qn[row];
    }
    __syncthreads();
    if (tid == 0) {                  // inclusive cumsum of g -> G
        float c = 0.f;
        for (int t = 0; t < 64; t++) { c += sG[t]; sG[t] = c; }
    }
    __syncthreads();

    // 64x64 gram matrices k.k^T and q.k^T, 4x4 register tiles
    int ti = tid >> 4, si = tid & 15;
    float accM[4][4] = {}, accA[4][4] = {};
    for (int d = 0; d < 128; d++) {
        float kt[4], qt[4], ks[4];
#pragma unroll
        for (int i = 0; i < 4; i++) {
            kt[i] = sk[(ti * 4 + i) * 129 + d];
            qt[i] = sq[(ti * 4 + i) * 129 + d];
        }
#pragma unroll
        for (int j = 0; j < 4; j++) ks[j] = sk[(si * 4 + j) * 129 + d];
#pragma unroll
        for (int i = 0; i < 4; i++)
#pragma unroll
            for (int j = 0; j < 4; j++) {
                accM[i][j] += kt[i] * ks[j];
                accA[i][j] += qt[i] * ks[j];
            }
    }
    int hc = hv * 64 + n;
#pragma unroll
    for (int i = 0; i < 4; i++) {
        int t = ti * 4 + i;
#pragma unroll
        for (int j = 0; j < 4; j++) {
            int s = si * 4 + j;
            float ed = expf(sG[t] - sG[s]);
            sM[t * 64 + s] = (s < t) ? sB[t] * ed * accM[i][j] : 0.f;
            g_A[((size_t)hc * 64 + t) * 64 + s] =
                (s <= t) ? SCALE_QK * ed * accA[i][j] : 0.f;
        }
    }
    if (tid < 64) {
        g_qds[hc * 64 + tid] = SCALE_QK * expf(sG[tid]);
        g_kds[hc * 64 + tid] = expf(sG[63] - sG[tid]);
        if (tid == 0) g_gce[hc] = expf(sG[63]);
    }
    __syncthreads();

    // Build fused rhs: sq <- beta*v ; sk <- beta*e^G*k (in place)
    for (int l = tid; l < 8192; l += 256) {
        int t = l >> 7, d = l & 127;
        sq[t * 129 + d] = sB[t] * g_v[(size_t)(n * 64 + t) * 4096 + hv * 128 + d];
        sk[t * 129 + d] *= sB[t] * expf(sG[t]);
    }
    __syncthreads();

    // Forward substitution (I+M) x = rhs: each thread owns one column.
    {
        float* buf = (tid < 128) ? sq : sk;
        int cc = tid & 127;
        for (int t = 1; t < 64; t++) {
            float acc = 0.f;
            for (int s = 0; s < t; s++) acc += sM[t * 64 + s] * buf[s * 129 + cc];
            buf[t * 129 + cc] -= acc;
        }
    }
    __syncthreads();

    size_t base = (size_t)hc * 8192;
    for (int l = tid; l < 8192; l += 256) {
        int t = l >> 7, d = l & 127;
        g_u0[base + l] = sq[t * 129 + d];
        g_W [base + l] = sk[t * 129 + d];
    }
}

// ------------------------- sequential scan over chunks ----------------------
// grid (32 heads, 4 DV-slices); S slice [128 x 32] resident in shared.
__global__ __launch_bounds__(256) void scan_kernel() {
    extern __shared__ float sm[];
    float* sS = sm;              // 128*32
    float* sW = sS + 4096;       // 64*132
    float* sQ = sW + 8448;       // 64*132
    float* sK = sQ + 8448;       // 64*132
    float* sA = sK + 8448;       // 64*65
    float* sU = sA + 4160;       // 64*32

    int hv = blockIdx.x, sl = blockIdx.y, hk = hv >> 1;
    int c0 = sl * 32;
    int tid = threadIdx.x;
    int tr = tid >> 3;           // 0..31
    int tc = tid & 7;            // 0..7 -> cols 4*tc

    for (int l = tid; l < 4096; l += 256) sS[l] = 0.f;
    __syncthreads();

    for (int n = 0; n < NCHUNK; n++) {
        int hc = hv * 64 + n;
        const float* Wp   = g_W   + (size_t)hc * 8192;
        const float* Ap   = g_A   + (size_t)hc * 4096;
        const float* u0p  = g_u0  + (size_t)hc * 8192;
        const float* qdsp = g_qds + hc * 64;
        const float* kdsp = g_kds + hc * 64;

        // ---- stage ----
        for (int l = tid; l < 4096; l += 256)
            sA[(l >> 6) * 65 + (l & 63)] = Ap[l];
        for (int l = tid; l < 2048; l += 256) {
            int t = l >> 5, j = l & 31;
            float4 wv = reinterpret_cast<const float4*>(Wp + t * 128)[j];
            *reinterpret_cast<float4*>(sW + t * 132 + j * 4) = wv;
            float qs = qdsp[t], ks = kdsp[t];
            const float* qrow = g_qn + (size_t)(n * 64 + t) * 2048 + hk * 128;
            const float* krow = g_kn + (size_t)(n * 64 + t) * 2048 + hk * 128;
            float4 qv = reinterpret_cast<const float4*>(qrow)[j];
            float4 kv = reinterpret_cast<const float4*>(krow)[j];
            qv.x *= qs; qv.y *= qs; qv.z *= qs; qv.w *= qs;
            kv.x *= ks; kv.y *= ks; kv.z *= ks; kv.w *= ks;
            *reinterpret_cast<float4*>(sQ + t * 132 + j * 4) = qv;
            *reinterpret_cast<float4*>(sK + t * 132 + j * 4) = kv;
        }
        __syncthreads();

        // ---- u = u0 - W @ S  (rows 2tr,2tr+1; cols 4tc..4tc+3) ----
        {
            float a0[4] = {0,0,0,0}, a1[4] = {0,0,0,0};
            int r0 = 2 * tr, r1 = 2 * tr + 1;
#pragma unroll 4
            for (int d = 0; d < 128; d++) {
                float w0 = sW[r0 * 132 + d], w1 = sW[r1 * 132 + d];
                float4 sv = *reinterpret_cast<const float4*>(sS + d * 32 + 4 * tc);
                a0[0] += w0 * sv.x; a0[1] += w0 * sv.y; a0[2] += w0 * sv.z; a0[3] += w0 * sv.w;
                a1[0] += w1 * sv.x; a1[1] += w1 * sv.y; a1[2] += w1 * sv.z; a1[3] += w1 * sv.w;
            }
            float4 u00 = *reinterpret_cast<const float4*>(u0p + r0 * 128 + c0 + 4 * tc);
            float4 u01 = *reinterpret_cast<const float4*>(u0p + r1 * 128 + c0 + 4 * tc);
            sU[r0 * 32 + 4 * tc + 0] = u00.x - a0[0];
            sU[r0 * 32 + 4 * tc + 1] = u00.y - a0[1];
            sU[r0 * 32 + 4 * tc + 2] = u00.z - a0[2];
            sU[r0 * 32 + 4 * tc + 3] = u00.w - a0[3];
            sU[r1 * 32 + 4 * tc + 0] = u01.x - a1[0];
            sU[r1 * 32 + 4 * tc + 1] = u01.y - a1[1];
            sU[r1 * 32 + 4 * tc + 2] = u01.z - a1[2];
            sU[r1 * 32 + 4 * tc + 3] = u01.w - a1[3];
        }
        __syncthreads();

        // ---- o = A @ u + qd @ S ----
        {
            float a0[4] = {0,0,0,0}, a1[4] = {0,0,0,0};
            int r0 = 2 * tr, r1 = 2 * tr + 1;
#pragma unroll 4
            for (int s = 0; s < 64; s++) {
                float p0 = sA[r0 * 65 + s], p1 = sA[r1 * 65 + s];
                float4 uv = *reinterpret_cast<const float4*>(sU + s * 32 + 4 * tc);
                a0[0] += p0 * uv.x; a0[1] += p0 * uv.y; a0[2] += p0 * uv.z; a0[3] += p0 * uv.w;
                a1[0] += p1 * uv.x; a1[1] += p1 * uv.y; a1[2] += p1 * uv.z; a1[3] += p1 * uv.w;
            }
#pragma unroll 4
            for (int d = 0; d < 128; d++) {
                float q0 = sQ[r0 * 132 + d], q1 = sQ[r1 * 132 + d];
                float4 sv = *reinterpret_cast<const float4*>(sS + d * 32 + 4 * tc);
                a0[0] += q0 * sv.x; a0[1] += q0 * sv.y; a0[2] += q0 * sv.z; a0[3] += q0 * sv.w;
                a1[0] += q1 * sv.x; a1[1] += q1 * sv.y; a1[2] += q1 * sv.z; a1[3] += q1 * sv.w;
            }
            float4 o0 = make_float4(a0[0], a0[1], a0[2], a0[3]);
            float4 o1 = make_float4(a1[0], a1[1], a1[2], a1[3]);
            *reinterpret_cast<float4*>(g_o + (size_t)(n * 64 + r0) * 4096 + hv * 128 + c0 + 4 * tc) = o0;
            *reinterpret_cast<float4*>(g_o + (size_t)(n * 64 + r1) * 4096 + hv * 128 + c0 + 4 * tc) = o1;
        }
        __syncthreads();

        // ---- S = e^gC * S + kd^T @ u  (4 d-rows x 4 cols per thread) ----
        {
            float acc[4][4] = {};
            int d0 = 4 * tr;       // tr 0..31 -> d rows 4tr..4tr+3
#pragma unroll 4
            for (int t = 0; t < 64; t++) {
                float4 kv = *reinterpret_cast<const float4*>(sK + t * 132 + d0);
                float4 uv = *reinterpret_cast<const float4*>(sU + t * 32 + 4 * tc);
                acc[0][0] += kv.x * uv.x; acc[0][1] += kv.x * uv.y; acc[0][2] += kv.x * uv.z; acc[0][3] += kv.x * uv.w;
                acc[1][0] += kv.y * uv.x; acc[1][1] += kv.y * uv.y; acc[1][2] += kv.y * uv.z; acc[1][3] += kv.y * uv.w;
                acc[2][0] += kv.z * uv.x; acc[2][1] += kv.z * uv.y; acc[2][2] += kv.z * uv.z; acc[2][3] += kv.z * uv.w;
                acc[3][0] += kv.w * uv.x; acc[3][1] += kv.w * uv.y; acc[3][2] += kv.w * uv.z; acc[3][3] += kv.w * uv.w;
            }
            float ge = g_gce[hc];
#pragma unroll
            for (int i = 0; i < 4; i++)
#pragma unroll
                for (int j = 0; j < 4; j++) {
                    int idx = (d0 + i) * 32 + 4 * tc + j;
                    sS[idx] = ge * sS[idx] + acc[i][j];
                }
        }
        __syncthreads();
    }
}

// ------------------------- gate (silu(z)) + rmsnorm -------------------------
__global__ void gate_kernel(const float* __restrict__ norm_weight) {
    int t = blockIdx.x, hv = blockIdx.y, d = threadIdx.x;
    int hk = hv >> 1, r = hv & 1;
    float o = g_o[(size_t)t * 4096 + hv * 128 + d];
    float z = g_qkvz[(size_t)t * QKVZ_COLS + hk * 768 + 512 + r * 128 + d];
    float xg = o * z / (1.f + expf(-z));
    float ms = blocksum128(xg * xg) * (1.f / 128.f);
    g_xg[(size_t)t * 4096 + hv * 128 + d] = xg * rsqrtf(ms + 1e-6f) * norm_weight[d];
}

// ------------------------- launch ------------------------------------------
extern "C" void kernel_launch(void* const* d_in, const int* in_sizes, int n_in,
                              void* d_out, int out_size) {
    const float* hidden      = (const float*)d_in[0];
    const float* W_qkvz      = (const float*)d_in[1];
    const float* W_ba        = (const float*)d_in[2];
    const float* conv_w      = (const float*)d_in[3];
    const float* dt_bias     = (const float*)d_in[4];
    const float* A_log       = (const float*)d_in[5];
    const float* norm_weight = (const float*)d_in[6];
    const float* W_out       = (const float*)d_in[7];
    float* out = (float*)d_out;

    float* qkvz; cudaGetSymbolAddress((void**)&qkvz, g_qkvz);
    float* ba;   cudaGetSymbolAddress((void**)&ba,   g_ba);
    float* xg;   cudaGetSymbolAddress((void**)&xg,   g_xg);

    cudaFuncSetAttribute(precompute_kernel,
        cudaFuncAttributeMaxDynamicSharedMemorySize, 82432);
    cudaFuncSetAttribute(scan_kernel,
        cudaFuncAttributeMaxDynamicSharedMemorySize, 142592);

    // 1. qkvz = hidden @ W_qkvz  [4096,2048]x[2048,12288]
    sgemm_kernel<128,128,16,8,8><<<dim3(QKVZ_COLS/128, T_LEN/128), 256>>>(
        hidden, W_qkvz, qkvz, T_LEN, QKVZ_COLS, DMODEL);
    // 2. ba = hidden @ W_ba  [4096,2048]x[2048,64]
    sgemm_kernel<128,64,16,8,4><<<dim3(1, T_LEN/128), 256>>>(
        hidden, W_ba, ba, T_LEN, 64, DMODEL);
    // 3. conv + silu
    conv_kernel<<<(T_LEN * 8192) / 256, 256>>>(conv_w);
    // 4. l2norm q,k
    l2norm_kernel<<<dim3(T_LEN * 16, 2), 128>>>();
    // 5. beta, g
    gbeta_kernel<<<(T_LEN * 32) / 256, 256>>>(A_log, dt_bias);
    // 6. per-chunk precompute
    precompute_kernel<<<dim3(NCHUNK, HVN), 256, 82432>>>();
    // 7. sequential scan
    scan_kernel<<<dim3(HVN, 4), 256, 142592>>>();
    // 8. gate + rmsnorm
    gate_kernel<<<dim3(T_LEN, HVN), 128>>>(norm_weight);
    // 9. out = xg @ W_out  [4096,4096]x[4096,2048]
    sgemm_kernel<128,128,16,8,8><<<dim3(DMODEL/128, T_LEN/128), 256>>>(
        xg, W_out, out, T_LEN, DMODEL, T_LEN);
}

// round 6
// speedup vs baseline: 2.0040x; 2.0040x over previous
#include <cuda_runtime.h>
#include <cuda_bf16.h>
#include <math.h>
#include <stdint.h>

#define T_LEN     4096
#define DMODEL    2048
#define HKN       16
#define HVN       32
#define NCHUNK    64
#define QKVZ_COLS 12288
#define SCALE_QK  0.08838834764831845f   // 1/sqrt(128)

// ------------------------- device scratch ----------------------------------
__device__ __align__(16) float g_qkvz[T_LEN * QKVZ_COLS];
__device__ __align__(16) float g_ba  [T_LEN * 64];
__device__ __align__(16) float g_qn  [T_LEN * 2048];
__device__ __align__(16) float g_kn  [T_LEN * 2048];
__device__ __align__(16) float g_v   [T_LEN * 4096];
__device__ __align__(16) float g_gv  [T_LEN * HVN];
__device__ __align__(16) float g_bv  [T_LEN * HVN];
__device__ __align__(16) float g_A   [HVN * NCHUNK * 64 * 64];
__device__ __align__(16) float g_u0  [HVN * NCHUNK * 64 * 128];
__device__ __align__(16) float g_W   [HVN * NCHUNK * 64 * 128];
__device__ __align__(16) float g_qds [HVN * NCHUNK * 64];
__device__ __align__(16) float g_kds [HVN * NCHUNK * 64];
__device__ __align__(16) float g_gce [HVN * NCHUNK];
__device__ __align__(16) float g_o   [T_LEN * 4096];
__device__ __align__(16) float g_xg  [T_LEN * 4096];

// bf16 hi/lo split operands for tensor-core GEMMs
__device__ __align__(16) __nv_bfloat16 g_hid_hi [T_LEN * DMODEL];
__device__ __align__(16) __nv_bfloat16 g_hid_lo [T_LEN * DMODEL];
__device__ __align__(16) __nv_bfloat16 g_wqkT_hi[QKVZ_COLS * DMODEL];
__device__ __align__(16) __nv_bfloat16 g_wqkT_lo[QKVZ_COLS * DMODEL];
__device__ __align__(16) __nv_bfloat16 g_xg_hi  [T_LEN * 4096];
__device__ __align__(16) __nv_bfloat16 g_xg_lo  [T_LEN * 4096];
__device__ __align__(16) __nv_bfloat16 g_woT_hi [DMODEL * 4096];
__device__ __align__(16) __nv_bfloat16 g_woT_lo [DMODEL * 4096];

// ------------------------- PTX helpers --------------------------------------
__device__ __forceinline__ uint32_t smem_u32(const void* p) {
    uint32_t a;
    asm("{ .reg .u64 t; cvta.to.shared.u64 t, %1; cvt.u32.u64 %0, t; }"
        : "=r"(a) : "l"(p));
    return a;
}
__device__ __forceinline__ void cp_async16(uint32_t saddr, const void* gaddr) {
    asm volatile("cp.async.cg.shared.global [%0], [%1], 16;"
                 :: "r"(saddr), "l"(gaddr));
}
__device__ __forceinline__ void cp_commit() {
    asm volatile("cp.async.commit_group;" ::: "memory");
}
template <int N>
__device__ __forceinline__ void cp_wait() {
    asm volatile("cp.async.wait_group %0;" :: "n"(N) : "memory");
}
__device__ __forceinline__ void ldmx4(uint32_t* r, uint32_t addr) {
    asm volatile("ldmatrix.sync.aligned.m8n8.x4.shared.b16 {%0,%1,%2,%3}, [%4];"
                 : "=r"(r[0]), "=r"(r[1]), "=r"(r[2]), "=r"(r[3]) : "r"(addr));
}
__device__ __forceinline__ void mma16816(float* c, const uint32_t* a,
                                         const uint32_t* b) {
    asm volatile(
        "mma.sync.aligned.m16n8k16.row.col.f32.bf16.bf16.f32 "
        "{%0,%1,%2,%3}, {%4,%5,%6,%7}, {%8,%9}, {%0,%1,%2,%3};"
        : "+f"(c[0]), "+f"(c[1]), "+f"(c[2]), "+f"(c[3])
        : "r"(a[0]), "r"(a[1]), "r"(a[2]), "r"(a[3]), "r"(b[0]), "r"(b[1]));
}

// ------------------------- HMMA split-bf16 GEMM ------------------------------
// C[M,N] = A[M,K] @ Bt^T where Bt is [N,K] row-major (K contiguous).
// A,Bt given as bf16 hi/lo pairs; products hh+hl+lh accumulated in fp32.
// grid(N/128, M/128), 256 threads (8 warps, 2x4), dyn smem = 2*64KB.
__global__ __launch_bounds__(256, 1) void gemm_mma_kernel(
    const __nv_bfloat16* __restrict__ Ahi, const __nv_bfloat16* __restrict__ Alo,
    const __nv_bfloat16* __restrict__ Bhi, const __nv_bfloat16* __restrict__ Blo,
    float* __restrict__ C, int M, int N, int K)
{
    extern __shared__ unsigned char gsm[];
    uint32_t sbase = smem_u32(gsm);
    int tid = threadIdx.x, wid = tid >> 5, lane = tid & 31;
    int bm = blockIdx.y * 128, bn = blockIdx.x * 128;
    int wr = wid >> 2, wc = wid & 3;          // warp 64x32 tile

    float acc[4][4][4];
#pragma unroll
    for (int i = 0; i < 4; i++)
#pragma unroll
        for (int j = 0; j < 4; j++)
#pragma unroll
            for (int l = 0; l < 4; l++) acc[i][j][l] = 0.f;

    const int NCH = K >> 6;

    auto issue = [&](int c) {
        int buf = c & 1, k0 = c << 6;
        uint32_t sb = sbase + buf * 65536;
#pragma unroll
        for (int tile = 0; tile < 4; tile++) {
            const __nv_bfloat16* src =
                (tile == 0) ? Ahi : (tile == 1) ? Alo : (tile == 2) ? Bhi : Blo;
            int row0 = (tile < 2) ? bm : bn;
            uint32_t sbt = sb + tile * 16384;
#pragma unroll
            for (int j = 0; j < 4; j++) {
                int b = j * 256 + tid;
                int r = b >> 3, cb = b & 7;
                const void* g = src + (size_t)(row0 + r) * K + k0 + cb * 8;
                uint32_t s = sbt + r * 128 + ((cb ^ (r & 7)) << 4);
                cp_async16(s, g);
            }
        }
        cp_commit();
    };

    issue(0);
    for (int c = 0; c < NCH; c++) {
        if (c + 1 < NCH) { issue(c + 1); cp_wait<1>(); }
        else             { cp_wait<0>(); }
        __syncthreads();

        uint32_t sA = sbase + (c & 1) * 65536;
        uint32_t sB = sA + 32768;
#pragma unroll
        for (int s = 0; s < 4; s++) {           // k16 steps within chunk
            uint32_t ah[4][4], al[4][4], bh[4][2], bl[4][2];
#pragma unroll
            for (int mt = 0; mt < 4; mt++) {
                int row = wr * 64 + mt * 16 + (lane & 15);
                int kb = s * 2 + (lane >> 4);
                uint32_t ad = sA + row * 128 + ((kb ^ (row & 7)) << 4);
                ldmx4(ah[mt], ad);
                ldmx4(al[mt], ad + 16384);
            }
#pragma unroll
            for (int bt = 0; bt < 2; bt++) {
                int rowb = wc * 32 + bt * 16 + ((lane >> 4) << 3) + (lane & 7);
                int kb = s * 2 + ((lane >> 3) & 1);
                uint32_t ad = sB + rowb * 128 + ((kb ^ (rowb & 7)) << 4);
                uint32_t t[4];
                ldmx4(t, ad);
                bh[2 * bt][0] = t[0]; bh[2 * bt][1] = t[1];
                bh[2 * bt + 1][0] = t[2]; bh[2 * bt + 1][1] = t[3];
                ldmx4(t, ad + 16384);
                bl[2 * bt][0] = t[0]; bl[2 * bt][1] = t[1];
                bl[2 * bt + 1][0] = t[2]; bl[2 * bt + 1][1] = t[3];
            }
#pragma unroll
            for (int mt = 0; mt < 4; mt++)
#pragma unroll
                for (int nt = 0; nt < 4; nt++) {
                    mma16816(acc[mt][nt], ah[mt], bh[nt]);
                    mma16816(acc[mt][nt], ah[mt], bl[nt]);
                    mma16816(acc[mt][nt], al[mt], bh[nt]);
                }
        }
        __syncthreads();
    }

    // epilogue
#pragma unroll
    for (int mt = 0; mt < 4; mt++) {
        int row = bm + wr * 64 + mt * 16 + (lane >> 2);
#pragma unroll
        for (int nt = 0; nt < 4; nt++) {
            int col = bn + wc * 32 + nt * 8 + (lane & 3) * 2;
            *reinterpret_cast<float2*>(C + (size_t)row * N + col) =
                make_float2(acc[mt][nt][0], acc[mt][nt][1]);
            *reinterpret_cast<float2*>(C + (size_t)(row + 8) * N + col) =
                make_float2(acc[mt][nt][2], acc[mt][nt][3]);
        }
    }
}

// ------------------------- split / transpose conversions --------------------
__global__ void split_kernel(const float* __restrict__ X,
                             __nv_bfloat16* __restrict__ hi,
                             __nv_bfloat16* __restrict__ lo) {
    int i = blockIdx.x * 256 + threadIdx.x;
    float x = X[i];
    __nv_bfloat16 h = __float2bfloat16(x);
    hi[i] = h;
    lo[i] = __float2bfloat16(x - __bfloat162float(h));
}

// W [K,N] fp32 -> Wt hi/lo [N,K] bf16. block (32,8), grid (N/32, K/32)
__global__ void transpose_split_kernel(const float* __restrict__ W,
                                       __nv_bfloat16* __restrict__ hi,
                                       __nv_bfloat16* __restrict__ lo,
                                       int K, int N) {
    __shared__ float tile[32][33];
    int n0 = blockIdx.x * 32, k0 = blockIdx.y * 32;
    int tx = threadIdx.x, ty = threadIdx.y;
    for (int i = ty; i < 32; i += 8)
        tile[i][tx] = W[(size_t)(k0 + i) * N + n0 + tx];
    __syncthreads();
    for (int i = ty; i < 32; i += 8) {
        float v = tile[tx][i];                 // = W[k0+tx][n0+i]
        __nv_bfloat16 h = __float2bfloat16(v);
        size_t o = (size_t)(n0 + i) * K + k0 + tx;
        hi[o] = h;
        lo[o] = __float2bfloat16(v - __bfloat162float(h));
    }
}

// ------------------------- small fp32 SGEMM (for ba) ------------------------
template<int BM, int BN, int BK, int TM, int TN>
__global__ __launch_bounds__(256) void sgemm_kernel(
    const float* __restrict__ A, const float* __restrict__ B,
    float* __restrict__ C, int M, int N, int K)
{
    __shared__ float As[BK][BM];
    __shared__ float Bs[BK][BN];
    const int THREADS = (BM / TM) * (BN / TN);
    int tid = threadIdx.x;
    int bm = blockIdx.y * BM, bn = blockIdx.x * BN;
    int tm = (tid / (BN / TN)) * TM;
    int tn = (tid % (BN / TN)) * TN;
    float acc[TM][TN] = {};
    for (int k0 = 0; k0 < K; k0 += BK) {
#pragma unroll
        for (int l = tid * 4; l < BM * BK; l += THREADS * 4) {
            int row = l / BK, kk = l % BK;
            float4 av = *reinterpret_cast<const float4*>(
                A + (size_t)(bm + row) * K + k0 + kk);
            As[kk + 0][row] = av.x; As[kk + 1][row] = av.y;
            As[kk + 2][row] = av.z; As[kk + 3][row] = av.w;
        }
#pragma unroll
        for (int l = tid * 4; l < BK * BN; l += THREADS * 4) {
            int rr = l / BN, cc = l % BN;
            *reinterpret_cast<float4*>(&Bs[rr][cc]) =
                *reinterpret_cast<const float4*>(B + (size_t)(k0 + rr) * N + bn + cc);
        }
        __syncthreads();
#pragma unroll
        for (int kk = 0; kk < BK; kk++) {
            float ar[TM], br[TN];
#pragma unroll
            for (int i = 0; i < TM; i++) ar[i] = As[kk][tm + i];
#pragma unroll
            for (int j = 0; j < TN; j++) br[j] = Bs[kk][tn + j];
#pragma unroll
            for (int i = 0; i < TM; i++)
#pragma unroll
                for (int j = 0; j < TN; j++) acc[i][j] = fmaf(ar[i], br[j], acc[i][j]);
        }
        __syncthreads();
    }
#pragma unroll
    for (int i = 0; i < TM; i++)
#pragma unroll
        for (int j = 0; j < TN; j++)
            C[(size_t)(bm + tm + i) * N + bn + tn + j] = acc[i][j];
}

// ------------------------- conv (K=4 causal) + silu -------------------------
__global__ void conv_kernel(const float* __restrict__ conv_w) {
    int idx = blockIdx.x * 256 + threadIdx.x;        // over T*8192
    int t = idx >> 13, c = idx & 8191;
    int col, didx; float* dst;
    if (c < 2048) {
        int h = c >> 7, d = c & 127;
        col = h * 768 + d; dst = g_qn; didx = t * 2048 + c;
    } else if (c < 4096) {
        int cc = c - 2048; int h = cc >> 7, d = cc & 127;
        col = h * 768 + 128 + d; dst = g_kn; didx = t * 2048 + cc;
    } else {
        int i = c - 4096; int hv = i >> 7, d = i & 127;
        col = (hv >> 1) * 768 + 256 + (hv & 1) * 128 + d;
        dst = g_v; didx = t * 4096 + i;
    }
    float w0 = conv_w[c * 4 + 0], w1 = conv_w[c * 4 + 1];
    float w2 = conv_w[c * 4 + 2], w3 = conv_w[c * 4 + 3];
    float acc = w3 * g_qkvz[(size_t)t * QKVZ_COLS + col];
    if (t >= 1) acc += w2 * g_qkvz[(size_t)(t - 1) * QKVZ_COLS + col];
    if (t >= 2) acc += w1 * g_qkvz[(size_t)(t - 2) * QKVZ_COLS + col];
    if (t >= 3) acc += w0 * g_qkvz[(size_t)(t - 3) * QKVZ_COLS + col];
    dst[didx] = acc / (1.f + expf(-acc));
}

// ------------------------- l2norm: warp per 128-row --------------------------
__global__ void l2norm_kernel() {
    int row = blockIdx.x * 8 + (threadIdx.x >> 5);   // 0 .. 2*65536-1
    float* p = (row < 65536) ? g_qn : g_kn;
    size_t base = (size_t)(row & 65535) * 128;
    int lane = threadIdx.x & 31;
    float4 v = *reinterpret_cast<const float4*>(p + base + lane * 4);
    float s = v.x * v.x + v.y * v.y + v.z * v.z + v.w * v.w;
#pragma unroll
    for (int o = 16; o; o >>= 1) s += __shfl_xor_sync(0xffffffffu, s, o);
    float r = rsqrtf(s + 1e-6f);
    v.x *= r; v.y *= r; v.z *= r; v.w *= r;
    *reinterpret_cast<float4*>(p + base + lane * 4) = v;
}

// ------------------------- beta / g ----------------------------------------
__global__ void gbeta_kernel(const float* __restrict__ A_log,
                             const float* __restrict__ dt_bias) {
    int idx = blockIdx.x * 256 + threadIdx.x;
    int t = idx >> 5, hv = idx & 31, hk = hv >> 1, r = hv & 1;
    float b = g_ba[t * 64 + hk * 4 + r];
    float a = g_ba[t * 64 + hk * 4 + 2 + r];
    g_bv[idx] = 1.f / (1.f + expf(-b));
    float x = a + dt_bias[hv];
    float sp = (x > 20.f) ? x : log1pf(expf(x));
    g_gv[idx] = -expf(A_log[hv]) * sp;
}

// ------------------------- per-(chunk,head) precompute ----------------------
__global__ __launch_bounds__(256) void precompute_kernel() {
    extern __shared__ float psm[];
    float* sk = psm;                 // 64*129
    float* sq = sk + 64 * 129;       // 64*129
    float* sM = sq + 64 * 129;       // 64*64
    __shared__ float sG[64], sB[64];
    int n = blockIdx.x, hv = blockIdx.y, hk = hv >> 1;
    int tid = threadIdx.x;

    if (tid < 64) {
        int t = n * 64 + tid;
        sB[tid] = g_bv[t * 32 + hv];
        sG[tid] = g_gv[t * 32 + hv];
    }
    for (int l = tid; l < 8192; l += 256) {
        int t = l >> 7, d = l & 127;
        size_t row = (size_t)(n * 64 + t) * 2048 + hk * 128 + d;
        sk[t * 129 + d] = g_kn[row];
        sq[t * 129 + d] = g_qn[row];
    }
    __syncthreads();
    if (tid == 0) {
        float c = 0.f;
        for (int t = 0; t < 64; t++) { c += sG[t]; sG[t] = c; }
    }
    __syncthreads();

    int ti = tid >> 4, si = tid & 15;
    float accM[4][4] = {}, accA[4][4] = {};
    for (int d = 0; d < 128; d++) {
        float kt[4], qt[4], ks[4];
#pragma unroll
        for (int i = 0; i < 4; i++) {
            kt[i] = sk[(ti * 4 + i) * 129 + d];
            qt[i] = sq[(ti * 4 + i) * 129 + d];
        }
#pragma unroll
        for (int j = 0; j < 4; j++) ks[j] = sk[(si * 4 + j) * 129 + d];
#pragma unroll
        for (int i = 0; i < 4; i++)
#pragma unroll
            for (int j = 0; j < 4; j++) {
                accM[i][j] += kt[i] * ks[j];
                accA[i][j] += qt[i] * ks[j];
            }
    }
    int hc = hv * 64 + n;
#pragma unroll
    for (int i = 0; i < 4; i++) {
        int t = ti * 4 + i;
#pragma unroll
        for (int j = 0; j < 4; j++) {
            int s = si * 4 + j;
            float ed = expf(sG[t] - sG[s]);
            sM[t * 64 + s] = (s < t) ? sB[t] * ed * accM[i][j] : 0.f;
            g_A[((size_t)hc * 64 + t) * 64 + s] =
                (s <= t) ? SCALE_QK * ed * accA[i][j] : 0.f;
        }
    }
    if (tid < 64) {
        g_qds[hc * 64 + tid] = SCALE_QK * expf(sG[tid]);
        g_kds[hc * 64 + tid] = expf(sG[63] - sG[tid]);
        if (tid == 0) g_gce[hc] = expf(sG[63]);
    }
    __syncthreads();

    for (int l = tid; l < 8192; l += 256) {
        int t = l >> 7, d = l & 127;
        sq[t * 129 + d] = sB[t] * g_v[(size_t)(n * 64 + t) * 4096 + hv * 128 + d];
        sk[t * 129 + d] *= sB[t] * expf(sG[t]);
    }
    __syncthreads();

    {
        float* buf = (tid < 128) ? sq : sk;
        int cc = tid & 127;
        for (int t = 1; t < 64; t++) {
            float acc = 0.f;
            for (int s = 0; s < t; s++) acc += sM[t * 64 + s] * buf[s * 129 + cc];
            buf[t * 129 + cc] -= acc;
        }
    }
    __syncthreads();

    size_t base = (size_t)hc * 8192;
    for (int l = tid; l < 8192; l += 256) {
        int t = l >> 7, d = l & 127;
        g_u0[base + l] = sq[t * 129 + d];
        g_W [base + l] = sk[t * 129 + d];
    }
}

// ------------------------- sequential scan over chunks ----------------------
__global__ __launch_bounds__(256) void scan_kernel() {
    extern __shared__ float sm[];
    float* sS = sm;              // 128*32
    float* sW = sS + 4096;       // 64*132
    float* sQ = sW + 8448;       // 64*132
    float* sK = sQ + 8448;       // 64*132
    float* sA = sK + 8448;       // 64*65
    float* sU = sA + 4160;       // 64*32

    int hv = blockIdx.x, sl = blockIdx.y, hk = hv >> 1;
    int c0 = sl * 32;
    int tid = threadIdx.x;
    int tr = tid >> 3;
    int tc = tid & 7;

    for (int l = tid; l < 4096; l += 256) sS[l] = 0.f;
    __syncthreads();

    for (int n = 0; n < NCHUNK; n++) {
        int hc = hv * 64 + n;
        const float* Wp   = g_W   + (size_t)hc * 8192;
        const float* Ap   = g_A   + (size_t)hc * 4096;
        const float* u0p  = g_u0  + (size_t)hc * 8192;
        const float* qdsp = g_qds + hc * 64;
        const float* kdsp = g_kds + hc * 64;

        for (int l = tid; l < 4096; l += 256)
            sA[(l >> 6) * 65 + (l & 63)] = Ap[l];
        for (int l = tid; l < 2048; l += 256) {
            int t = l >> 5, j = l & 31;
            float4 wv = reinterpret_cast<const float4*>(Wp + t * 128)[j];
            *reinterpret_cast<float4*>(sW + t * 132 + j * 4) = wv;
            float qs = qdsp[t], ks = kdsp[t];
            const float* qrow = g_qn + (size_t)(n * 64 + t) * 2048 + hk * 128;
            const float* krow = g_kn + (size_t)(n * 64 + t) * 2048 + hk * 128;
            float4 qv = reinterpret_cast<const float4*>(qrow)[j];
            float4 kv = reinterpret_cast<const float4*>(krow)[j];
            qv.x *= qs; qv.y *= qs; qv.z *= qs; qv.w *= qs;
            kv.x *= ks; kv.y *= ks; kv.z *= ks; kv.w *= ks;
            *reinterpret_cast<float4*>(sQ + t * 132 + j * 4) = qv;
            *reinterpret_cast<float4*>(sK + t * 132 + j * 4) = kv;
        }
        __syncthreads();

        {   // u = u0 - W @ S
            float a0[4] = {0,0,0,0}, a1[4] = {0,0,0,0};
            int r0 = 2 * tr, r1 = 2 * tr + 1;
#pragma unroll 4
            for (int d = 0; d < 128; d++) {
                float w0 = sW[r0 * 132 + d], w1 = sW[r1 * 132 + d];
                float4 sv = *reinterpret_cast<const float4*>(sS + d * 32 + 4 * tc);
                a0[0] += w0 * sv.x; a0[1] += w0 * sv.y; a0[2] += w0 * sv.z; a0[3] += w0 * sv.w;
                a1[0] += w1 * sv.x; a1[1] += w1 * sv.y; a1[2] += w1 * sv.z; a1[3] += w1 * sv.w;
            }
            float4 u00 = *reinterpret_cast<const float4*>(u0p + r0 * 128 + c0 + 4 * tc);
            float4 u01 = *reinterpret_cast<const float4*>(u0p + r1 * 128 + c0 + 4 * tc);
            sU[r0 * 32 + 4 * tc + 0] = u00.x - a0[0];
            sU[r0 * 32 + 4 * tc + 1] = u00.y - a0[1];
            sU[r0 * 32 + 4 * tc + 2] = u00.z - a0[2];
            sU[r0 * 32 + 4 * tc + 3] = u00.w - a0[3];
            sU[r1 * 32 + 4 * tc + 0] = u01.x - a1[0];
            sU[r1 * 32 + 4 * tc + 1] = u01.y - a1[1];
            sU[r1 * 32 + 4 * tc + 2] = u01.z - a1[2];
            sU[r1 * 32 + 4 * tc + 3] = u01.w - a1[3];
        }
        __syncthreads();

        {   // o = A @ u + qd @ S
            float a0[4] = {0,0,0,0}, a1[4] = {0,0,0,0};
            int r0 = 2 * tr, r1 = 2 * tr + 1;
#pragma unroll 4
            for (int s = 0; s < 64; s++) {
                float p0 = sA[r0 * 65 + s], p1 = sA[r1 * 65 + s];
                float4 uv = *reinterpret_cast<const float4*>(sU + s * 32 + 4 * tc);
                a0[0] += p0 * uv.x; a0[1] += p0 * uv.y; a0[2] += p0 * uv.z; a0[3] += p0 * uv.w;
                a1[0] += p1 * uv.x; a1[1] += p1 * uv.y; a1[2] += p1 * uv.z; a1[3] += p1 * uv.w;
            }
#pragma unroll 4
            for (int d = 0; d < 128; d++) {
                float q0 = sQ[r0 * 132 + d], q1 = sQ[r1 * 132 + d];
                float4 sv = *reinterpret_cast<const float4*>(sS + d * 32 + 4 * tc);
                a0[0] += q0 * sv.x; a0[1] += q0 * sv.y; a0[2] += q0 * sv.z; a0[3] += q0 * sv.w;
                a1[0] += q1 * sv.x; a1[1] += q1 * sv.y; a1[2] += q1 * sv.z; a1[3] += q1 * sv.w;
            }
            *reinterpret_cast<float4*>(g_o + (size_t)(n * 64 + r0) * 4096 + hv * 128 + c0 + 4 * tc) =
                make_float4(a0[0], a0[1], a0[2], a0[3]);
            *reinterpret_cast<float4*>(g_o + (size_t)(n * 64 + r1) * 4096 + hv * 128 + c0 + 4 * tc) =
                make_float4(a1[0], a1[1], a1[2], a1[3]);
        }
        __syncthreads();

        {   // S = e^gC * S + kd^T @ u
            float acc[4][4] = {};
            int d0 = 4 * tr;
#pragma unroll 4
            for (int t = 0; t < 64; t++) {
                float4 kv = *reinterpret_cast<const float4*>(sK + t * 132 + d0);
                float4 uv = *reinterpret_cast<const float4*>(sU + t * 32 + 4 * tc);
                acc[0][0] += kv.x * uv.x; acc[0][1] += kv.x * uv.y; acc[0][2] += kv.x * uv.z; acc[0][3] += kv.x * uv.w;
                acc[1][0] += kv.y * uv.x; acc[1][1] += kv.y * uv.y; acc[1][2] += kv.y * uv.z; acc[1][3] += kv.y * uv.w;
                acc[2][0] += kv.z * uv.x; acc[2][1] += kv.z * uv.y; acc[2][2] += kv.z * uv.z; acc[2][3] += kv.z * uv.w;
                acc[3][0] += kv.w * uv.x; acc[3][1] += kv.w * uv.y; acc[3][2] += kv.w * uv.z; acc[3][3] += kv.w * uv.w;
            }
            float ge = g_gce[hc];
#pragma unroll
            for (int i = 0; i < 4; i++)
#pragma unroll
                for (int j = 0; j < 4; j++) {
                    int idx = (d0 + i) * 32 + 4 * tc + j;
                    sS[idx] = ge * sS[idx] + acc[i][j];
                }
        }
        __syncthreads();
    }
}

// ------------------------- gate (silu(z)) + rmsnorm -------------------------
__device__ __forceinline__ float blocksum128(float v) {
#pragma unroll
    for (int o = 16; o; o >>= 1) v += __shfl_xor_sync(0xffffffffu, v, o);
    __shared__ float ws[4];
    if ((threadIdx.x & 31) == 0) ws[threadIdx.x >> 5] = v;
    __syncthreads();
    return ws[0] + ws[1] + ws[2] + ws[3];
}
__global__ void gate_kernel(const float* __restrict__ norm_weight) {
    int t = blockIdx.x, hv = blockIdx.y, d = threadIdx.x;
    int hk = hv >> 1, r = hv & 1;
    float o = g_o[(size_t)t * 4096 + hv * 128 + d];
    float z = g_qkvz[(size_t)t * QKVZ_COLS + hk * 768 + 512 + r * 128 + d];
    float xg = o * z / (1.f + expf(-z));
    float ms = blocksum128(xg * xg) * (1.f / 128.f);
    g_xg[(size_t)t * 4096 + hv * 128 + d] = xg * rsqrtf(ms + 1e-6f) * norm_weight[d];
}

// ------------------------- launch ------------------------------------------
extern "C" void kernel_launch(void* const* d_in, const int* in_sizes, int n_in,
                              void* d_out, int out_size) {
    const float* hidden      = (const float*)d_in[0];
    const float* W_qkvz      = (const float*)d_in[1];
    const float* W_ba        = (const float*)d_in[2];
    const float* conv_w      = (const float*)d_in[3];
    const float* dt_bias     = (const float*)d_in[4];
    const float* A_log       = (const float*)d_in[5];
    const float* norm_weight = (const float*)d_in[6];
    const float* W_out       = (const float*)d_in[7];
    float* out = (float*)d_out;

    float* qkvz; cudaGetSymbolAddress((void**)&qkvz, g_qkvz);
    float* ba;   cudaGetSymbolAddress((void**)&ba,   g_ba);
    float* xg;   cudaGetSymbolAddress((void**)&xg,   g_xg);
    __nv_bfloat16 *hid_hi, *hid_lo, *wqk_hi, *wqk_lo, *xg_hi, *xg_lo, *wo_hi, *wo_lo;
    cudaGetSymbolAddress((void**)&hid_hi, g_hid_hi);
    cudaGetSymbolAddress((void**)&hid_lo, g_hid_lo);
    cudaGetSymbolAddress((void**)&wqk_hi, g_wqkT_hi);
    cudaGetSymbolAddress((void**)&wqk_lo, g_wqkT_lo);
    cudaGetSymbolAddress((void**)&xg_hi,  g_xg_hi);
    cudaGetSymbolAddress((void**)&xg_lo,  g_xg_lo);
    cudaGetSymbolAddress((void**)&wo_hi,  g_woT_hi);
    cudaGetSymbolAddress((void**)&wo_lo,  g_woT_lo);

    const int GEMM_SMEM = 2 * 65536;   // 131072
    cudaFuncSetAttribute(gemm_mma_kernel,
        cudaFuncAttributeMaxDynamicSharedMemorySize, GEMM_SMEM);
    cudaFuncSetAttribute(precompute_kernel,
        cudaFuncAttributeMaxDynamicSharedMemorySize, 82432);
    cudaFuncSetAttribute(scan_kernel,
        cudaFuncAttributeMaxDynamicSharedMemorySize, 142592);

    // 0. conversions for GEMM 1
    split_kernel<<<(T_LEN * DMODEL) / 256, 256>>>(hidden, hid_hi, hid_lo);
    transpose_split_kernel<<<dim3(QKVZ_COLS / 32, DMODEL / 32), dim3(32, 8)>>>(
        W_qkvz, wqk_hi, wqk_lo, DMODEL, QKVZ_COLS);
    transpose_split_kernel<<<dim3(DMODEL / 32, T_LEN / 32), dim3(32, 8)>>>(
        W_out, wo_hi, wo_lo, T_LEN, DMODEL);

    // 1. qkvz = hidden @ W_qkvz (HMMA, split bf16)
    gemm_mma_kernel<<<dim3(QKVZ_COLS / 128, T_LEN / 128), 256, GEMM_SMEM>>>(
        hid_hi, hid_lo, wqk_hi, wqk_lo, qkvz, T_LEN, QKVZ_COLS, DMODEL);
    // 2. ba = hidden @ W_ba (fp32, tiny)
    sgemm_kernel<128, 64, 16, 8, 4><<<dim3(1, T_LEN / 128), 256>>>(
        hidden, W_ba, ba, T_LEN, 64, DMODEL);
    // 3. conv + silu
    conv_kernel<<<(T_LEN * 8192) / 256, 256>>>(conv_w);
    // 4. l2norm q,k (warp per row)
    l2norm_kernel<<<(2 * T_LEN * 16) / 8, 256>>>();
    // 5. beta, g
    gbeta_kernel<<<(T_LEN * 32) / 256, 256>>>(A_log, dt_bias);
    // 6. per-chunk precompute
    precompute_kernel<<<dim3(NCHUNK, HVN), 256, 82432>>>();
    // 7. sequential scan
    scan_kernel<<<dim3(HVN, 4), 256, 142592>>>();
    // 8. gate + rmsnorm
    gate_kernel<<<dim3(T_LEN, HVN), 128>>>(norm_weight);
    // 9. out = xg @ W_out (HMMA, split bf16)
    split_kernel<<<(T_LEN * 4096) / 256, 256>>>(xg, xg_hi, xg_lo);
    gemm_mma_kernel<<<dim3(DMODEL / 128, T_LEN / 128), 256, GEMM_SMEM>>>(
        xg_hi, xg_lo, wo_hi, wo_lo, out, T_LEN, DMODEL, T_LEN);
}

// round 8
// speedup vs baseline: 2.0223x; 1.0091x over previous
#include <cuda_runtime.h>
#include <cuda_bf16.h>
#include <math.h>
#include <stdint.h>

#define T_LEN     4096
#define DMODEL    2048
#define HKN       16
#define HVN       32
#define NCHUNK    64
#define QKVZ_COLS 12288
#define SCALE_QK  0.08838834764831845f   // 1/sqrt(128)

// ------------------------- device scratch ----------------------------------
__device__ __align__(16) float g_qkvz[T_LEN * QKVZ_COLS];
__device__ __align__(16) float g_ba  [T_LEN * 64];
__device__ __align__(16) float g_qn  [T_LEN * 2048];
__device__ __align__(16) float g_kn  [T_LEN * 2048];
__device__ __align__(16) float g_v   [T_LEN * 4096];
__device__ __align__(16) float g_gv  [T_LEN * HVN];
__device__ __align__(16) float g_bv  [T_LEN * HVN];
__device__ __align__(16) float g_A   [HVN * NCHUNK * 64 * 64];
__device__ __align__(16) float g_u0  [HVN * NCHUNK * 64 * 128];
__device__ __align__(16) float g_W   [HVN * NCHUNK * 64 * 128];
__device__ __align__(16) float g_qds [HVN * NCHUNK * 64];
__device__ __align__(16) float g_kds [HVN * NCHUNK * 64];
__device__ __align__(16) float g_gce [HVN * NCHUNK];
__device__ __align__(16) float g_o   [T_LEN * 4096];

// bf16 hi/lo split operands for tensor-core GEMMs
__device__ __align__(16) __nv_bfloat16 g_hid_hi [T_LEN * DMODEL];
__device__ __align__(16) __nv_bfloat16 g_hid_lo [T_LEN * DMODEL];
__device__ __align__(16) __nv_bfloat16 g_wqkT_hi[QKVZ_COLS * DMODEL];
__device__ __align__(16) __nv_bfloat16 g_wqkT_lo[QKVZ_COLS * DMODEL];
__device__ __align__(16) __nv_bfloat16 g_xg_hi  [T_LEN * 4096];
__device__ __align__(16) __nv_bfloat16 g_xg_lo  [T_LEN * 4096];
__device__ __align__(16) __nv_bfloat16 g_woT_hi [DMODEL * 4096];
__device__ __align__(16) __nv_bfloat16 g_woT_lo [DMODEL * 4096];

// ------------------------- PTX helpers --------------------------------------
__device__ __forceinline__ uint32_t smem_u32(const void* p) {
    uint32_t a;
    asm("{ .reg .u64 t; cvta.to.shared.u64 t, %1; cvt.u32.u64 %0, t; }"
        : "=r"(a) : "l"(p));
    return a;
}
__device__ __forceinline__ void cp_async16(uint32_t saddr, const void* gaddr) {
    asm volatile("cp.async.cg.shared.global [%0], [%1], 16;"
                 :: "r"(saddr), "l"(gaddr));
}
__device__ __forceinline__ void cp_commit() {
    asm volatile("cp.async.commit_group;" ::: "memory");
}
template <int N>
__device__ __forceinline__ void cp_wait() {
    asm volatile("cp.async.wait_group %0;" :: "n"(N) : "memory");
}
__device__ __forceinline__ void ldmx4(uint32_t* r, uint32_t addr) {
    asm volatile("ldmatrix.sync.aligned.m8n8.x4.shared.b16 {%0,%1,%2,%3}, [%4];"
                 : "=r"(r[0]), "=r"(r[1]), "=r"(r[2]), "=r"(r[3]) : "r"(addr));
}
__device__ __forceinline__ void mma16816(float* c, const uint32_t* a,
                                         const uint32_t* b) {
    asm volatile(
        "mma.sync.aligned.m16n8k16.row.col.f32.bf16.bf16.f32 "
        "{%0,%1,%2,%3}, {%4,%5,%6,%7}, {%8,%9}, {%0,%1,%2,%3};"
        : "+f"(c[0]), "+f"(c[1]), "+f"(c[2]), "+f"(c[3])
        : "r"(a[0]), "r"(a[1]), "r"(a[2]), "r"(a[3]), "r"(b[0]), "r"(b[1]));
}

// ------------------------- HMMA split-bf16 GEMM ------------------------------
// C[M,N] = A[M,K] @ Bt^T, Bt [N,K] row-major; hi/lo pairs, hh+hl+lh in fp32.
// grid(N/128, M/128), 512 threads (16 warps, 4x4 of 32x32), 3-stage cp.async.
__global__ __launch_bounds__(512, 1) void gemm_mma_kernel(
    const __nv_bfloat16* __restrict__ Ahi, const __nv_bfloat16* __restrict__ Alo,
    const __nv_bfloat16* __restrict__ Bhi, const __nv_bfloat16* __restrict__ Blo,
    float* __restrict__ C, int M, int N, int K)
{
    extern __shared__ unsigned char gsm[];
    uint32_t sbase = smem_u32(gsm);
    int tid = threadIdx.x, wid = tid >> 5, lane = tid & 31;
    int bm = blockIdx.y * 128, bn = blockIdx.x * 128;
    int wr = wid >> 2, wc = wid & 3;          // warp 32x32 tile

    float acc[2][4][4];
#pragma unroll
    for (int i = 0; i < 2; i++)
#pragma unroll
        for (int j = 0; j < 4; j++)
#pragma unroll
            for (int l = 0; l < 4; l++) acc[i][j][l] = 0.f;

    const int NCH = K >> 6;

    auto issue = [&](int c) {
        int buf = c % 3, k0 = c << 6;
        uint32_t sb = sbase + buf * 65536;
#pragma unroll
        for (int tile = 0; tile < 4; tile++) {
            const __nv_bfloat16* src =
                (tile == 0) ? Ahi : (tile == 1) ? Alo : (tile == 2) ? Bhi : Blo;
            int row0 = (tile < 2) ? bm : bn;
            uint32_t sbt = sb + tile * 16384;
#pragma unroll
            for (int j = 0; j < 2; j++) {
                int b = j * 512 + tid;
                int r = b >> 3, cb = b & 7;
                const void* g = src + (size_t)(row0 + r) * K + k0 + cb * 8;
                uint32_t s = sbt + r * 128 + ((cb ^ (r & 7)) << 4);
                cp_async16(s, g);
            }
        }
        cp_commit();
    };

    issue(0);
    if (NCH > 1) issue(1);
    for (int c = 0; c < NCH; c++) {
        if (c + 2 < NCH)      { issue(c + 2); cp_wait<2>(); }
        else if (c + 1 < NCH) { cp_wait<1>(); }
        else                  { cp_wait<0>(); }
        __syncthreads();

        uint32_t sA = sbase + (c % 3) * 65536;
        uint32_t sB = sA + 32768;
#pragma unroll
        for (int s = 0; s < 4; s++) {           // k16 steps within chunk
            uint32_t ah[2][4], al[2][4], bh[4][2], bl[4][2];
#pragma unroll
            for (int mt = 0; mt < 2; mt++) {
                int row = wr * 32 + mt * 16 + (lane & 15);
                int kb = s * 2 + (lane >> 4);
                uint32_t ad = sA + row * 128 + ((kb ^ (row & 7)) << 4);
                ldmx4(ah[mt], ad);
                ldmx4(al[mt], ad + 16384);
            }
#pragma unroll
            for (int bt = 0; bt < 2; bt++) {
                int rowb = wc * 32 + bt * 16 + ((lane >> 4) << 3) + (lane & 7);
                int kb = s * 2 + ((lane >> 3) & 1);
                uint32_t ad = sB + rowb * 128 + ((kb ^ (rowb & 7)) << 4);
                uint32_t t[4];
                ldmx4(t, ad);
                bh[2 * bt][0] = t[0]; bh[2 * bt][1] = t[1];
                bh[2 * bt + 1][0] = t[2]; bh[2 * bt + 1][1] = t[3];
                ldmx4(t, ad + 16384);
                bl[2 * bt][0] = t[0]; bl[2 * bt][1] = t[1];
                bl[2 * bt + 1][0] = t[2]; bl[2 * bt + 1][1] = t[3];
            }
#pragma unroll
            for (int mt = 0; mt < 2; mt++)
#pragma unroll
                for (int nt = 0; nt < 4; nt++) {
                    mma16816(acc[mt][nt], ah[mt], bh[nt]);
                    mma16816(acc[mt][nt], ah[mt], bl[nt]);
                    mma16816(acc[mt][nt], al[mt], bh[nt]);
                }
        }
        __syncthreads();
    }

    // epilogue
#pragma unroll
    for (int mt = 0; mt < 2; mt++) {
        int row = bm + wr * 32 + mt * 16 + (lane >> 2);
#pragma unroll
        for (int nt = 0; nt < 4; nt++) {
            int col = bn + wc * 32 + nt * 8 + (lane & 3) * 2;
            *reinterpret_cast<float2*>(C + (size_t)row * N + col) =
                make_float2(acc[mt][nt][0], acc[mt][nt][1]);
            *reinterpret_cast<float2*>(C + (size_t)(row + 8) * N + col) =
                make_float2(acc[mt][nt][2], acc[mt][nt][3]);
        }
    }
}

// ------------------------- split / transpose conversions --------------------
__global__ void split_kernel(const float* __restrict__ X,
                             __nv_bfloat16* __restrict__ hi,
                             __nv_bfloat16* __restrict__ lo) {
    int i = blockIdx.x * 256 + threadIdx.x;
    float x = X[i];
    __nv_bfloat16 h = __float2bfloat16(x);
    hi[i] = h;
    lo[i] = __float2bfloat16(x - __bfloat162float(h));
}

// W [K,N] fp32 -> Wt hi/lo [N,K] bf16. block (32,8), grid (N/32, K/32)
__global__ void transpose_split_kernel(const float* __restrict__ W,
                                       __nv_bfloat16* __restrict__ hi,
                                       __nv_bfloat16* __restrict__ lo,
                                       int K, int N) {
    __shared__ float tile[32][33];
    int n0 = blockIdx.x * 32, k0 = blockIdx.y * 32;
    int tx = threadIdx.x, ty = threadIdx.y;
    for (int i = ty; i < 32; i += 8)
        tile[i][tx] = W[(size_t)(k0 + i) * N + n0 + tx];
    __syncthreads();
    for (int i = ty; i < 32; i += 8) {
        float v = tile[tx][i];                 // = W[k0+tx][n0+i]
        __nv_bfloat16 h = __float2bfloat16(v);
        size_t o = (size_t)(n0 + i) * K + k0 + tx;
        hi[o] = h;
        lo[o] = __float2bfloat16(v - __bfloat162float(h));
    }
}

// ------------------------- small fp32 SGEMM (for ba) ------------------------
template<int BM, int BN, int BK, int TM, int TN>
__global__ __launch_bounds__(256) void sgemm_kernel(
    const float* __restrict__ A, const float* __restrict__ B,
    float* __restrict__ C, int M, int N, int K)
{
    __shared__ float As[BK][BM];
    __shared__ float Bs[BK][BN];
    const int THREADS = (BM / TM) * (BN / TN);
    int tid = threadIdx.x;
    int bm = blockIdx.y * BM, bn = blockIdx.x * BN;
    int tm = (tid / (BN / TN)) * TM;
    int tn = (tid % (BN / TN)) * TN;
    float acc[TM][TN] = {};
    for (int k0 = 0; k0 < K; k0 += BK) {
#pragma unroll
        for (int l = tid * 4; l < BM * BK; l += THREADS * 4) {
            int row = l / BK, kk = l % BK;
            float4 av = *reinterpret_cast<const float4*>(
                A + (size_t)(bm + row) * K + k0 + kk);
            As[kk + 0][row] = av.x; As[kk + 1][row] = av.y;
            As[kk + 2][row] = av.z; As[kk + 3][row] = av.w;
        }
#pragma unroll
        for (int l = tid * 4; l < BK * BN; l += THREADS * 4) {
            int rr = l / BN, cc = l % BN;
            *reinterpret_cast<float4*>(&Bs[rr][cc]) =
                *reinterpret_cast<const float4*>(B + (size_t)(k0 + rr) * N + bn + cc);
        }
        __syncthreads();
#pragma unroll
        for (int kk = 0; kk < BK; kk++) {
            float ar[TM], br[TN];
#pragma unroll
            for (int i = 0; i < TM; i++) ar[i] = As[kk][tm + i];
#pragma unroll
            for (int j = 0; j < TN; j++) br[j] = Bs[kk][tn + j];
#pragma unroll
            for (int i = 0; i < TM; i++)
#pragma unroll
                for (int j = 0; j < TN; j++) acc[i][j] = fmaf(ar[i], br[j], acc[i][j]);
        }
        __syncthreads();
    }
#pragma unroll
    for (int i = 0; i < TM; i++)
#pragma unroll
        for (int j = 0; j < TN; j++)
            C[(size_t)(bm + tm + i) * N + bn + tn + j] = acc[i][j];
}

// ------------------------- conv (K=4 causal) + silu -------------------------
__global__ void conv_kernel(const float* __restrict__ conv_w) {
    int idx = blockIdx.x * 256 + threadIdx.x;        // over T*8192
    int t = idx >> 13, c = idx & 8191;
    int col, didx; float* dst;
    if (c < 2048) {
        int h = c >> 7, d = c & 127;
        col = h * 768 + d; dst = g_qn; didx = t * 2048 + c;
    } else if (c < 4096) {
        int cc = c - 2048; int h = cc >> 7, d = cc & 127;
        col = h * 768 + 128 + d; dst = g_kn; didx = t * 2048 + cc;
    } else {
        int i = c - 4096; int hv = i >> 7, d = i & 127;
        col = (hv >> 1) * 768 + 256 + (hv & 1) * 128 + d;
        dst = g_v; didx = t * 4096 + i;
    }
    float w0 = conv_w[c * 4 + 0], w1 = conv_w[c * 4 + 1];
    float w2 = conv_w[c * 4 + 2], w3 = conv_w[c * 4 + 3];
    float acc = w3 * g_qkvz[(size_t)t * QKVZ_COLS + col];
    if (t >= 1) acc += w2 * g_qkvz[(size_t)(t - 1) * QKVZ_COLS + col];
    if (t >= 2) acc += w1 * g_qkvz[(size_t)(t - 2) * QKVZ_COLS + col];
    if (t >= 3) acc += w0 * g_qkvz[(size_t)(t - 3) * QKVZ_COLS + col];
    dst[didx] = acc / (1.f + expf(-acc));
}

// ------------------------- l2norm: warp per 128-row --------------------------
__global__ void l2norm_kernel() {
    int row = blockIdx.x * 8 + (threadIdx.x >> 5);   // 0 .. 2*65536-1
    float* p = (row < 65536) ? g_qn : g_kn;
    size_t base = (size_t)(row & 65535) * 128;
    int lane = threadIdx.x & 31;
    float4 v = *reinterpret_cast<const float4*>(p + base + lane * 4);
    float s = v.x * v.x + v.y * v.y + v.z * v.z + v.w * v.w;
#pragma unroll
    for (int o = 16; o; o >>= 1) s += __shfl_xor_sync(0xffffffffu, s, o);
    float r = rsqrtf(s + 1e-6f);
    v.x *= r; v.y *= r; v.z *= r; v.w *= r;
    *reinterpret_cast<float4*>(p + base + lane * 4) = v;
}

// ------------------------- beta / g ----------------------------------------
__global__ void gbeta_kernel(const float* __restrict__ A_log,
                             const float* __restrict__ dt_bias) {
    int idx = blockIdx.x * 256 + threadIdx.x;
    int t = idx >> 5, hv = idx & 31, hk = hv >> 1, r = hv & 1;
    float b = g_ba[t * 64 + hk * 4 + r];
    float a = g_ba[t * 64 + hk * 4 + 2 + r];
    g_bv[idx] = 1.f / (1.f + expf(-b));
    float x = a + dt_bias[hv];
    float sp = (x > 20.f) ? x : log1pf(expf(x));
    g_gv[idx] = -expf(A_log[hv]) * sp;
}

// ------------------------- per-(chunk,head) precompute ----------------------
__global__ __launch_bounds__(256) void precompute_kernel() {
    extern __shared__ float psm[];
    float* sk = psm;                 // 64*129
    float* sq = sk + 64 * 129;       // 64*129
    float* sM = sq + 64 * 129;       // 64*64
    __shared__ float sG[64], sB[64];
    int n = blockIdx.x, hv = blockIdx.y, hk = hv >> 1;
    int tid = threadIdx.x;

    if (tid < 64) {
        int t = n * 64 + tid;
        sB[tid] = g_bv[t * 32 + hv];
        sG[tid] = g_gv[t * 32 + hv];
    }
    for (int l = tid; l < 8192; l += 256) {
        int t = l >> 7, d = l & 127;
        size_t row = (size_t)(n * 64 + t) * 2048 + hk * 128 + d;
        sk[t * 129 + d] = g_kn[row];
        sq[t * 129 + d] = g_qn[row];
    }
    __syncthreads();
    if (tid == 0) {
        float c = 0.f;
        for (int t = 0; t < 64; t++) { c += sG[t]; sG[t] = c; }
    }
    __syncthreads();

    int ti = tid >> 4, si = tid & 15;
    float accM[4][4] = {}, accA[4][4] = {};
    for (int d = 0; d < 128; d++) {
        float kt[4], qt[4], ks[4];
#pragma unroll
        for (int i = 0; i < 4; i++) {
            kt[i] = sk[(ti * 4 + i) * 129 + d];
            qt[i] = sq[(ti * 4 + i) * 129 + d];
        }
#pragma unroll
        for (int j = 0; j < 4; j++) ks[j] = sk[(si * 4 + j) * 129 + d];
#pragma unroll
        for (int i = 0; i < 4; i++)
#pragma unroll
            for (int j = 0; j < 4; j++) {
                accM[i][j] += kt[i] * ks[j];
                accA[i][j] += qt[i] * ks[j];
            }
    }
    int hc = hv * 64 + n;
#pragma unroll
    for (int i = 0; i < 4; i++) {
        int t = ti * 4 + i;
#pragma unroll
        for (int j = 0; j < 4; j++) {
            int s = si * 4 + j;
            float ed = expf(sG[t] - sG[s]);
            sM[t * 64 + s] = (s < t) ? sB[t] * ed * accM[i][j] : 0.f;
            g_A[((size_t)hc * 64 + t) * 64 + s] =
                (s <= t) ? SCALE_QK * ed * accA[i][j] : 0.f;
        }
    }
    if (tid < 64) {
        g_qds[hc * 64 + tid] = SCALE_QK * expf(sG[tid]);
        g_kds[hc * 64 + tid] = expf(sG[63] - sG[tid]);
        if (tid == 0) g_gce[hc] = expf(sG[63]);
    }
    __syncthreads();

    for (int l = tid; l < 8192; l += 256) {
        int t = l >> 7, d = l & 127;
        sq[t * 129 + d] = sB[t] * g_v[(size_t)(n * 64 + t) * 4096 + hv * 128 + d];
        sk[t * 129 + d] *= sB[t] * expf(sG[t]);
    }
    __syncthreads();

    {
        float* buf = (tid < 128) ? sq : sk;
        int cc = tid & 127;
        for (int t = 1; t < 64; t++) {
            float acc = 0.f;
            for (int s = 0; s < t; s++) acc += sM[t * 64 + s] * buf[s * 129 + cc];
            buf[t * 129 + cc] -= acc;
        }
    }
    __syncthreads();

    size_t base = (size_t)hc * 8192;
    for (int l = tid; l < 8192; l += 256) {
        int t = l >> 7, d = l & 127;
        g_u0[base + l] = sq[t * 129 + d];
        g_W [base + l] = sk[t * 129 + d];
    }
}

// ------------------------- sequential scan over chunks ----------------------
__global__ __launch_bounds__(256) void scan_kernel() {
    extern __shared__ float sm[];
    float* sS = sm;              // 128*32
    float* sW = sS + 4096;       // 64*132
    float* sQ = sW + 8448;       // 64*132
    float* sK = sQ + 8448;       // 64*132
    float* sA = sK + 8448;       // 64*65
    float* sU = sA + 4160;       // 64*32

    int hv = blockIdx.x, sl = blockIdx.y, hk = hv >> 1;
    int c0 = sl * 32;
    int tid = threadIdx.x;
    int tr = tid >> 3;
    int tc = tid & 7;

    for (int l = tid; l < 4096; l += 256) sS[l] = 0.f;
    __syncthreads();

    for (int n = 0; n < NCHUNK; n++) {
        int hc = hv * 64 + n;
        const float* Wp   = g_W   + (size_t)hc * 8192;
        const float* Ap   = g_A   + (size_t)hc * 4096;
        const float* u0p  = g_u0  + (size_t)hc * 8192;
        const float* qdsp = g_qds + hc * 64;
        const float* kdsp = g_kds + hc * 64;

        for (int l = tid; l < 4096; l += 256)
            sA[(l >> 6) * 65 + (l & 63)] = Ap[l];
        for (int l = tid; l < 2048; l += 256) {
            int t = l >> 5, j = l & 31;
            float4 wv = reinterpret_cast<const float4*>(Wp + t * 128)[j];
            *reinterpret_cast<float4*>(sW + t * 132 + j * 4) = wv;
            float qs = qdsp[t], ks = kdsp[t];
            const float* qrow = g_qn + (size_t)(n * 64 + t) * 2048 + hk * 128;
            const float* krow = g_kn + (size_t)(n * 64 + t) * 2048 + hk * 128;
            float4 qv = reinterpret_cast<const float4*>(qrow)[j];
            float4 kv = reinterpret_cast<const float4*>(krow)[j];
            qv.x *= qs; qv.y *= qs; qv.z *= qs; qv.w *= qs;
            kv.x *= ks; kv.y *= ks; kv.z *= ks; kv.w *= ks;
            *reinterpret_cast<float4*>(sQ + t * 132 + j * 4) = qv;
            *reinterpret_cast<float4*>(sK + t * 132 + j * 4) = kv;
        }
        __syncthreads();

        {   // u = u0 - W @ S
            float a0[4] = {0,0,0,0}, a1[4] = {0,0,0,0};
            int r0 = 2 * tr, r1 = 2 * tr + 1;
#pragma unroll 4
            for (int d = 0; d < 128; d++) {
                float w0 = sW[r0 * 132 + d], w1 = sW[r1 * 132 + d];
                float4 sv = *reinterpret_cast<const float4*>(sS + d * 32 + 4 * tc);
                a0[0] += w0 * sv.x; a0[1] += w0 * sv.y; a0[2] += w0 * sv.z; a0[3] += w0 * sv.w;
                a1[0] += w1 * sv.x; a1[1] += w1 * sv.y; a1[2] += w1 * sv.z; a1[3] += w1 * sv.w;
            }
            float4 u00 = *reinterpret_cast<const float4*>(u0p + r0 * 128 + c0 + 4 * tc);
            float4 u01 = *reinterpret_cast<const float4*>(u0p + r1 * 128 + c0 + 4 * tc);
            sU[r0 * 32 + 4 * tc + 0] = u00.x - a0[0];
            sU[r0 * 32 + 4 * tc + 1] = u00.y - a0[1];
            sU[r0 * 32 + 4 * tc + 2] = u00.z - a0[2];
            sU[r0 * 32 + 4 * tc + 3] = u00.w - a0[3];
            sU[r1 * 32 + 4 * tc + 0] = u01.x - a1[0];
            sU[r1 * 32 + 4 * tc + 1] = u01.y - a1[1];
            sU[r1 * 32 + 4 * tc + 2] = u01.z - a1[2];
            sU[r1 * 32 + 4 * tc + 3] = u01.w - a1[3];
        }
        __syncthreads();

        {   // o = A @ u + qd @ S
            float a0[4] = {0,0,0,0}, a1[4] = {0,0,0,0};
            int r0 = 2 * tr, r1 = 2 * tr + 1;
#pragma unroll 4
            for (int s = 0; s < 64; s++) {
                float p0 = sA[r0 * 65 + s], p1 = sA[r1 * 65 + s];
                float4 uv = *reinterpret_cast<const float4*>(sU + s * 32 + 4 * tc);
                a0[0] += p0 * uv.x; a0[1] += p0 * uv.y; a0[2] += p0 * uv.z; a0[3] += p0 * uv.w;
                a1[0] += p1 * uv.x; a1[1] += p1 * uv.y; a1[2] += p1 * uv.z; a1[3] += p1 * uv.w;
            }
#pragma unroll 4
            for (int d = 0; d < 128; d++) {
                float q0 = sQ[r0 * 132 + d], q1 = sQ[r1 * 132 + d];
                float4 sv = *reinterpret_cast<const float4*>(sS + d * 32 + 4 * tc);
                a0[0] += q0 * sv.x; a0[1] += q0 * sv.y; a0[2] += q0 * sv.z; a0[3] += q0 * sv.w;
                a1[0] += q1 * sv.x; a1[1] += q1 * sv.y; a1[2] += q1 * sv.z; a1[3] += q1 * sv.w;
            }
            *reinterpret_cast<float4*>(g_o + (size_t)(n * 64 + r0) * 4096 + hv * 128 + c0 + 4 * tc) =
                make_float4(a0[0], a0[1], a0[2], a0[3]);
            *reinterpret_cast<float4*>(g_o + (size_t)(n * 64 + r1) * 4096 + hv * 128 + c0 + 4 * tc) =
                make_float4(a1[0], a1[1], a1[2], a1[3]);
        }
        __syncthreads();

        {   // S = e^gC * S + kd^T @ u
            float acc[4][4] = {};
            int d0 = 4 * tr;
#pragma unroll 4
            for (int t = 0; t < 64; t++) {
                float4 kv = *reinterpret_cast<const float4*>(sK + t * 132 + d0);
                float4 uv = *reinterpret_cast<const float4*>(sU + t * 32 + 4 * tc);
                acc[0][0] += kv.x * uv.x; acc[0][1] += kv.x * uv.y; acc[0][2] += kv.x * uv.z; acc[0][3] += kv.x * uv.w;
                acc[1][0] += kv.y * uv.x; acc[1][1] += kv.y * uv.y; acc[1][2] += kv.y * uv.z; acc[1][3] += kv.y * uv.w;
                acc[2][0] += kv.z * uv.x; acc[2][1] += kv.z * uv.y; acc[2][2] += kv.z * uv.z; acc[2][3] += kv.z * uv.w;
                acc[3][0] += kv.w * uv.x; acc[3][1] += kv.w * uv.y; acc[3][2] += kv.w * uv.z; acc[3][3] += kv.w * uv.w;
            }
            float ge = g_gce[hc];
#pragma unroll
            for (int i = 0; i < 4; i++)
#pragma unroll
                for (int j = 0; j < 4; j++) {
                    int idx = (d0 + i) * 32 + 4 * tc + j;
                    sS[idx] = ge * sS[idx] + acc[i][j];
                }
        }
        __syncthreads();
    }
}

// ------------------------- gate (silu(z)) + rmsnorm + split -----------------
__device__ __forceinline__ float blocksum128(float v) {
#pragma unroll
    for (int o = 16; o; o >>= 1) v += __shfl_xor_sync(0xffffffffu, v, o);
    __shared__ float ws[4];
    if ((threadIdx.x & 31) == 0) ws[threadIdx.x >> 5] = v;
    __syncthreads();
    return ws[0] + ws[1] + ws[2] + ws[3];
}
__global__ void gate_kernel(const float* __restrict__ norm_weight) {
    int t = blockIdx.x, hv = blockIdx.y, d = threadIdx.x;
    int hk = hv >> 1, r = hv & 1;
    float o = g_o[(size_t)t * 4096 + hv * 128 + d];
    float z = g_qkvz[(size_t)t * QKVZ_COLS + hk * 768 + 512 + r * 128 + d];
    float xg = o * z / (1.f + expf(-z));
    float ms = blocksum128(xg * xg) * (1.f / 128.f);
    float v = xg * rsqrtf(ms + 1e-6f) * norm_weight[d];
    size_t idx = (size_t)t * 4096 + hv * 128 + d;
    __nv_bfloat16 h = __float2bfloat16(v);
    g_xg_hi[idx] = h;
    g_xg_lo[idx] = __float2bfloat16(v - __bfloat162float(h));
}

// ------------------------- launch ------------------------------------------
extern "C" void kernel_launch(void* const* d_in, const int* in_sizes, int n_in,
                              void* d_out, int out_size) {
    const float* hidden      = (const float*)d_in[0];
    const float* W_qkvz      = (const float*)d_in[1];
    const float* W_ba        = (const float*)d_in[2];
    const float* conv_w      = (const float*)d_in[3];
    const float* dt_bias     = (const float*)d_in[4];
    const float* A_log       = (const float*)d_in[5];
    const float* norm_weight = (const float*)d_in[6];
    const float* W_out       = (const float*)d_in[7];
    float* out = (float*)d_out;

    float* qkvz; cudaGetSymbolAddress((void**)&qkvz, g_qkvz);
    float* ba;   cudaGetSymbolAddress((void**)&ba,   g_ba);
    __nv_bfloat16 *hid_hi, *hid_lo, *wqk_hi, *wqk_lo, *xg_hi, *xg_lo, *wo_hi, *wo_lo;
    cudaGetSymbolAddress((void**)&hid_hi, g_hid_hi);
    cudaGetSymbolAddress((void**)&hid_lo, g_hid_lo);
    cudaGetSymbolAddress((void**)&wqk_hi, g_wqkT_hi);
    cudaGetSymbolAddress((void**)&wqk_lo, g_wqkT_lo);
    cudaGetSymbolAddress((void**)&xg_hi,  g_xg_hi);
    cudaGetSymbolAddress((void**)&xg_lo,  g_xg_lo);
    cudaGetSymbolAddress((void**)&wo_hi,  g_woT_hi);
    cudaGetSymbolAddress((void**)&wo_lo,  g_woT_lo);

    const int GEMM_SMEM = 3 * 65536;   // 196608
    cudaFuncSetAttribute(gemm_mma_kernel,
        cudaFuncAttributeMaxDynamicSharedMemorySize, GEMM_SMEM);
    cudaFuncSetAttribute(precompute_kernel,
        cudaFuncAttributeMaxDynamicSharedMemorySize, 82432);
    cudaFuncSetAttribute(scan_kernel,
        cudaFuncAttributeMaxDynamicSharedMemorySize, 142592);

    // 0. conversions for GEMM 1
    split_kernel<<<(T_LEN * DMODEL) / 256, 256>>>(hidden, hid_hi, hid_lo);
    transpose_split_kernel<<<dim3(QKVZ_COLS / 32, DMODEL / 32), dim3(32, 8)>>>(
        W_qkvz, wqk_hi, wqk_lo, DMODEL, QKVZ_COLS);
    transpose_split_kernel<<<dim3(DMODEL / 32, T_LEN / 32), dim3(32, 8)>>>(
        W_out, wo_hi, wo_lo, T_LEN, DMODEL);

    // 1. qkvz = hidden @ W_qkvz (HMMA, split bf16)
    gemm_mma_kernel<<<dim3(QKVZ_COLS / 128, T_LEN / 128), 512, GEMM_SMEM>>>(
        hid_hi, hid_lo, wqk_hi, wqk_lo, qkvz, T_LEN, QKVZ_COLS, DMODEL);
    // 2. ba = hidden @ W_ba (fp32)
    sgemm_kernel<64, 64, 16, 4, 4><<<dim3(1, T_LEN / 64), 256>>>(
        hidden, W_ba, ba, T_LEN, 64, DMODEL);
    // 3. conv + silu
    conv_kernel<<<(T_LEN * 8192) / 256, 256>>>(conv_w);
    // 4. l2norm q,k (warp per row)
    l2norm_kernel<<<(2 * T_LEN * 16) / 8, 256>>>();
    // 5. beta, g
    gbeta_kernel<<<(T_LEN * 32) / 256, 256>>>(A_log, dt_bias);
    // 6. per-chunk precompute
    precompute_kernel<<<dim3(NCHUNK, HVN), 256, 82432>>>();
    // 7. sequential scan
    scan_kernel<<<dim3(HVN, 4), 256, 142592>>>();
    // 8. gate + rmsnorm + split (fused)
    gate_kernel<<<dim3(T_LEN, HVN), 128>>>(norm_weight);
    // 9. out = xg @ W_out (HMMA, split bf16)
    gemm_mma_kernel<<<dim3(DMODEL / 128, T_LEN / 128), 512, GEMM_SMEM>>>(
        xg_hi, xg_lo, wo_hi, wo_lo, out, T_LEN, DMODEL, T_LEN);
}